// round 7
// baseline (speedup 1.0000x reference)
#include <cuda_runtime.h>
#include <cuda_fp16.h>
#include <cstdint>

#define N_NODES 100000
#define D_FEAT  128
#define HIDDEN  128
#define M_TILE  128
#define KPAD    136          // fp16 row stride (272 B) -> conflict-free fragment loads

// ---------------------------------------------------------------------------
// Global scratch.  A/B stored fp16 (51 MB working set -> L2-resident gathers).
// ---------------------------------------------------------------------------
__device__ __half g_A[N_NODES * HIDDEN];       // x @ W1[:128] + b1
__device__ __half g_B[N_NODES * HIDDEN];       // x @ W1[128:]

// ---------------------------------------------------------------------------
// Stage 1: C[128 nodes][256 cols] per CTA via mma.sync m16n8k16 fp16 (fp32 acc).
// 512 threads, 16 warps in 4x4 grid of 32(M) x 64(N) warp tiles, single pass.
// W1 (fp32) is converted/transposed into smem by every CTA directly (no prep
// kernel): 128 KB coalesced read, L2-resident across CTAs.
// SMEM: sX [128][KPAD] + sW [256][KPAD] fp16 = 104448 B -> 2 CTAs/SM.
// ---------------------------------------------------------------------------
#define SM_X 0
#define SM_W 34816
#define SMEM_TOTAL 104448

static __device__ __forceinline__ void mma_fp16(
    float c[4], const uint32_t a[4], const uint32_t b[2])
{
    asm volatile(
        "mma.sync.aligned.m16n8k16.row.col.f32.f16.f16.f32 "
        "{%0,%1,%2,%3}, {%4,%5,%6,%7}, {%8,%9}, {%0,%1,%2,%3};"
        : "+f"(c[0]), "+f"(c[1]), "+f"(c[2]), "+f"(c[3])
        : "r"(a[0]), "r"(a[1]), "r"(a[2]), "r"(a[3]), "r"(b[0]), "r"(b[1]));
}

__global__ __launch_bounds__(512) void node_gemm_kernel(
    const float* __restrict__ x,
    const float* __restrict__ W1,
    const float* __restrict__ b1)
{
    extern __shared__ char smem[];
    __half* sX = (__half*)(smem + SM_X);
    __half* sW = (__half*)(smem + SM_W);

    const int tid     = threadIdx.x;
    const int m_block = blockIdx.x * M_TILE;

    // ---- convert W1 (fp32 [256][128]) into sW[n][k] fp16
    //      Wfull[k][n]: n<128 -> W1[k][n]; n>=128 -> W1[128+k][n-128]
    #pragma unroll 4
    for (int i = tid * 2; i < 256 * 128; i += 512 * 2) {
        int r = i >> 7, c = i & 127;
        float2 v = *(const float2*)&W1[i];
        int k = (r < 128) ? r : (r - 128);
        int n = (r < 128) ? c : (c + 128);
        sW[n * KPAD + k]       = __float2half_rn(v.x);
        sW[(n + 1) * KPAD + k] = __float2half_rn(v.y);
    }

    // ---- load X tile (128 x 128 fp32) -> fp16
    for (int i = tid; i < M_TILE * 64; i += 512) {
        int m = i >> 6;
        int k = (i & 63) * 2;
        int gm = m_block + m;
        float2 v = make_float2(0.f, 0.f);
        if (gm < N_NODES) v = *(const float2*)&x[gm * D_FEAT + k];
        *(__half2*)&sX[m * KPAD + k] = __floats2half2_rn(v.x, v.y);
    }
    __syncthreads();

    // ---- warp tiling: 16 warps, each 32(M) x 64(N)
    const int wid  = tid >> 5;
    const int lane = tid & 31;
    const int g    = lane >> 2;
    const int t    = lane & 3;
    const int mrow0 = (wid & 3) * 32;
    const int ncol0 = (wid >> 2) * 64;     // 0,64,128,192

    float acc[2][8][4];
    #pragma unroll
    for (int mt = 0; mt < 2; mt++)
        #pragma unroll
        for (int nt = 0; nt < 8; nt++)
            #pragma unroll
            for (int r = 0; r < 4; r++) acc[mt][nt][r] = 0.f;

    #pragma unroll
    for (int ks = 0; ks < 8; ks++) {
        const int k0 = ks * 16;
        uint32_t a[2][4];
        #pragma unroll
        for (int mt = 0; mt < 2; mt++) {
            const int rb = mrow0 + mt * 16;
            a[mt][0] = *(const uint32_t*)&sX[(rb + g)     * KPAD + k0 + t * 2];
            a[mt][1] = *(const uint32_t*)&sX[(rb + g + 8) * KPAD + k0 + t * 2];
            a[mt][2] = *(const uint32_t*)&sX[(rb + g)     * KPAD + k0 + t * 2 + 8];
            a[mt][3] = *(const uint32_t*)&sX[(rb + g + 8) * KPAD + k0 + t * 2 + 8];
        }
        #pragma unroll
        for (int nt = 0; nt < 8; nt++) {
            const int cb = ncol0 + nt * 8;
            uint32_t b[2];
            b[0] = *(const uint32_t*)&sW[(cb + g) * KPAD + k0 + t * 2];
            b[1] = *(const uint32_t*)&sW[(cb + g) * KPAD + k0 + t * 2 + 8];
            mma_fp16(acc[0][nt], a[0], b);
            mma_fp16(acc[1][nt], a[1], b);
        }
    }

    // ---- epilogue: +b1 (A-half), fp16 store
    const bool isA = (ncol0 < 128);
    __half* halfp = isA ? g_A : g_B;
    const int clocal0 = isA ? ncol0 : (ncol0 - 128);

    float2 bb[8];
    #pragma unroll
    for (int nt = 0; nt < 8; nt++) {
        if (isA) bb[nt] = *(const float2*)&b1[ncol0 + nt * 8 + t * 2];
        else     bb[nt] = make_float2(0.f, 0.f);
    }
    #pragma unroll
    for (int mt = 0; mt < 2; mt++) {
        const int node0 = m_block + mrow0 + mt * 16 + g;
        const int node1 = node0 + 8;
        #pragma unroll
        for (int nt = 0; nt < 8; nt++) {
            const int c = clocal0 + nt * 8 + t * 2;
            if (node0 < N_NODES)
                *(__half2*)&halfp[(size_t)node0 * HIDDEN + c] =
                    __floats2half2_rn(acc[mt][nt][0] + bb[nt].x, acc[mt][nt][1] + bb[nt].y);
            if (node1 < N_NODES)
                *(__half2*)&halfp[(size_t)node1 * HIDDEN + c] =
                    __floats2half2_rn(acc[mt][nt][2] + bb[nt].x, acc[mt][nt][3] + bb[nt].y);
        }
    }
}

// ---------------------------------------------------------------------------
// Stage 2 (R5 form, proven fastest): half-warp per edge, 2 edges per
// half-warp per iteration (4 row-gathers in flight per half-warp).
// ---------------------------------------------------------------------------
static __device__ __forceinline__ float tanh_fast(float x) {
    float y;
    asm("tanh.approx.f32 %0, %1;" : "=f"(y) : "f"(x));
    return y;
}

__global__ __launch_bounds__(256) void edge_kernel(
    const void*  __restrict__ idx,
    const float* __restrict__ W2,
    const float* __restrict__ b2,
    float*       __restrict__ out,
    int E)
{
    const int lane = threadIdx.x & 31;
    const int hw   = lane >> 4;
    const int hl   = lane & 15;
    const int gwarp = (blockIdx.x * blockDim.x + threadIdx.x) >> 5;
    const int nwarps = (gridDim.x * blockDim.x) >> 5;

    const int* w32 = (const int*)idx;
    const bool is64 = ((w32[1] | w32[3] | w32[5] | w32[7]) == 0);
    const long long* p64 = (const long long*)idx;

    float wv[8];
    {
        float4 w0 = *(const float4*)&W2[hl * 8];
        float4 w1 = *(const float4*)&W2[hl * 8 + 4];
        wv[0] = w0.x; wv[1] = w0.y; wv[2] = w0.z; wv[3] = w0.w;
        wv[4] = w1.x; wv[5] = w1.y; wv[6] = w1.z; wv[7] = w1.w;
    }
    const float bias2 = b2[0];

    const uint4* Au = (const uint4*)g_A;   // 16 uint4 per row
    const uint4* Bu = (const uint4*)g_B;

    const int Q = (E + 3) >> 2;            // quads of edges
    for (int p = gwarp; p < Q; p += nwarps) {
        const int e0 = p * 4 + hw * 2;
        const int e1 = e0 + 1;
        const bool v0 = (e0 < E), v1 = (e1 < E);
        const int c0 = v0 ? e0 : (E - 1);
        const int c1 = v1 ? e1 : (E - 1);

        int s0, d0, s1, d1;
        if (is64) {
            s0 = (int)p64[c0]; d0 = (int)p64[E + c0];
            s1 = (int)p64[c1]; d1 = (int)p64[E + c1];
        } else {
            s0 = w32[c0];      d0 = w32[E + c0];
            s1 = w32[c1];      d1 = w32[E + c1];
        }

        uint4 ua0 = Au[(size_t)s0 * 16 + hl];
        uint4 ub0 = Bu[(size_t)d0 * 16 + hl];
        uint4 ua1 = Au[(size_t)s1 * 16 + hl];
        uint4 ub1 = Bu[(size_t)d1 * 16 + hl];

        float acc0 = 0.f, acc1 = 0.f;
        {
            const uint32_t* pa0 = (const uint32_t*)&ua0;
            const uint32_t* pb0 = (const uint32_t*)&ub0;
            const uint32_t* pa1 = (const uint32_t*)&ua1;
            const uint32_t* pb1 = (const uint32_t*)&ub1;
            #pragma unroll
            for (int q = 0; q < 4; q++) {
                float2 af0 = __half22float2(*(const __half2*)&pa0[q]);
                float2 bf0 = __half22float2(*(const __half2*)&pb0[q]);
                float2 af1 = __half22float2(*(const __half2*)&pa1[q]);
                float2 bf1 = __half22float2(*(const __half2*)&pb1[q]);
                acc0 = fmaf(tanh_fast(af0.x + bf0.x), wv[q * 2],     acc0);
                acc0 = fmaf(tanh_fast(af0.y + bf0.y), wv[q * 2 + 1], acc0);
                acc1 = fmaf(tanh_fast(af1.x + bf1.x), wv[q * 2],     acc1);
                acc1 = fmaf(tanh_fast(af1.y + bf1.y), wv[q * 2 + 1], acc1);
            }
        }

        #pragma unroll
        for (int off = 8; off; off >>= 1) {
            acc0 += __shfl_xor_sync(0xffffffffu, acc0, off);
            acc1 += __shfl_xor_sync(0xffffffffu, acc1, off);
        }

        if (hl == 0) {
            if (v0) out[e0] = __fdividef(1.0f, 1.0f + __expf(-(acc0 + bias2)));
            if (v1) out[e1] = __fdividef(1.0f, 1.0f + __expf(-(acc1 + bias2)));
        }
    }
}

// ---------------------------------------------------------------------------
extern "C" void kernel_launch(void* const* d_in, const int* in_sizes, int n_in,
                              void* d_out, int out_size)
{
    const float* x   = (const float*)d_in[0];
    const void*  idx = d_in[1];
    const float* W1  = (const float*)d_in[2];
    const float* b1  = (const float*)d_in[3];
    const float* W2  = (const float*)d_in[4];
    const float* b2  = (const float*)d_in[5];
    float* out = (float*)d_out;

    const int E = in_sizes[1] / 2;

    cudaFuncSetAttribute(node_gemm_kernel,
                         cudaFuncAttributeMaxDynamicSharedMemorySize, SMEM_TOTAL);

    const int n_tiles = (N_NODES + M_TILE - 1) / M_TILE;   // 782
    node_gemm_kernel<<<n_tiles, 512, SMEM_TOTAL>>>(x, W1, b1);

    edge_kernel<<<1184, 256>>>(idx, W2, b2, out, E);
}

// round 8
// speedup vs baseline: 1.4895x; 1.4895x over previous
#include <cuda_runtime.h>
#include <cuda_fp16.h>
#include <cstdint>

#define N_NODES 100000
#define D_FEAT  128
#define HIDDEN  128
#define M_TILE  128
#define KPAD    136          // fp16 row stride (272 B): LDSM-conflict-free (17 mod 8 = 1)
#define KPADB   272          // bytes

// ---------------------------------------------------------------------------
// Global scratch.  A/B stored fp16 (51 MB working set -> L2-resident gathers).
// ---------------------------------------------------------------------------
__device__ __half g_A[N_NODES * HIDDEN];       // x @ W1[:128] + b1
__device__ __half g_B[N_NODES * HIDDEN];       // x @ W1[128:]

// ---------------------------------------------------------------------------
// Stage 1: persistent GEMM.  grid=296 CTAs x 512 thr; each CTA converts W1
// (fp32 [256][128] -> fp16 k-major smem, fully coalesced) ONCE, then loops
// over M-tiles.  A frags via ldmatrix.x4, B frags via ldmatrix.x4.trans.
// SMEM: sW [256][KPAD] (69632 B) + sX [128][KPAD] (34816 B) = 104448 -> 2 CTAs/SM.
// ---------------------------------------------------------------------------
#define SM_W 0
#define SM_X 69632
#define SMEM_TOTAL 104448

static __device__ __forceinline__ uint32_t smem_u32(const void* p) {
    uint32_t a;
    asm("{ .reg .u64 t; cvta.to.shared.u64 t, %1; cvt.u32.u64 %0, t; }" : "=r"(a) : "l"(p));
    return a;
}

static __device__ __forceinline__ void mma_fp16(
    float c[4], const uint32_t a[4], uint32_t b0, uint32_t b1)
{
    asm volatile(
        "mma.sync.aligned.m16n8k16.row.col.f32.f16.f16.f32 "
        "{%0,%1,%2,%3}, {%4,%5,%6,%7}, {%8,%9}, {%0,%1,%2,%3};"
        : "+f"(c[0]), "+f"(c[1]), "+f"(c[2]), "+f"(c[3])
        : "r"(a[0]), "r"(a[1]), "r"(a[2]), "r"(a[3]), "r"(b0), "r"(b1));
}

static __device__ __forceinline__ void ldsm_x4(
    uint32_t r[4], uint32_t addr)
{
    asm volatile("ldmatrix.sync.aligned.m8n8.x4.shared.b16 {%0,%1,%2,%3}, [%4];"
                 : "=r"(r[0]), "=r"(r[1]), "=r"(r[2]), "=r"(r[3]) : "r"(addr));
}
static __device__ __forceinline__ void ldsm_x4_t(
    uint32_t r[4], uint32_t addr)
{
    asm volatile("ldmatrix.sync.aligned.m8n8.x4.trans.shared.b16 {%0,%1,%2,%3}, [%4];"
                 : "=r"(r[0]), "=r"(r[1]), "=r"(r[2]), "=r"(r[3]) : "r"(addr));
}

__global__ __launch_bounds__(512) void node_gemm_kernel(
    const float* __restrict__ x,
    const float* __restrict__ W1,
    const float* __restrict__ b1,
    int n_tiles)
{
    extern __shared__ char smem[];
    __half* sW = (__half*)(smem + SM_W);
    __half* sX = (__half*)(smem + SM_X);
    const uint32_t wbase = smem_u32(sW);
    const uint32_t xbase = smem_u32(sX);

    const int tid = threadIdx.x;

    // ---- convert W1 once: sW[r][c] = fp16(W1[r][c]), contiguous both sides
    #pragma unroll 4
    for (int i = tid * 2; i < 256 * 128; i += 512 * 2) {
        int r = i >> 7, c = i & 127;
        float2 v = *(const float2*)&W1[i];
        *(__half2*)&sW[r * KPAD + c] = __floats2half2_rn(v.x, v.y);
    }

    // ---- warp geometry
    const int wid  = tid >> 5;
    const int lane = tid & 31;
    const int g    = lane >> 2;
    const int t    = lane & 3;
    const int mrow0 = (wid & 3) * 32;
    const int ncol0 = (wid >> 2) * 64;         // 0,64,128,192
    const bool isA  = (ncol0 < 128);
    const int nloc0 = isA ? ncol0 : (ncol0 - 128);
    const int krowb = isA ? 0 : 128;           // W rows for this half

    // ldmatrix per-lane addressing
    const int lrow = (lane & 7) + ((lane >> 3) & 1) * 8;   // 0..15
    const int lsel = lane >> 4;                            // 0/1

    // A tile base (per mt): row = mrow0 + mt*16 + lrow, col halves = lsel*8
    uint32_t aoff[2];
    #pragma unroll
    for (int mt = 0; mt < 2; mt++)
        aoff[mt] = xbase + (uint32_t)((mrow0 + mt * 16 + lrow) * KPADB + lsel * 16);
    // B tile base (per nt-pair p): row = krowb + lrow (+k0), col = nloc0 + p*16 + lsel*8
    uint32_t boff[4];
    #pragma unroll
    for (int p = 0; p < 4; p++)
        boff[p] = wbase + (uint32_t)((krowb + lrow) * KPADB + (nloc0 + p * 16 + lsel * 8) * 2);

    // bias for A-half columns
    float2 bb[8];
    #pragma unroll
    for (int nt = 0; nt < 8; nt++) {
        if (isA) bb[nt] = *(const float2*)&b1[ncol0 + nt * 8 + t * 2];
        else     bb[nt] = make_float2(0.f, 0.f);
    }
    __half* halfp = isA ? g_A : g_B;

    // ---- tile loop
    for (int tile = blockIdx.x; tile < n_tiles; tile += gridDim.x) {
        const int m_block = tile * M_TILE;

        // load X tile (128 x 128 fp32) -> fp16 row-major [m][k]
        for (int i = tid; i < M_TILE * 64; i += 512) {
            int m = i >> 6;
            int k = (i & 63) * 2;
            int gm = m_block + m;
            float2 v = make_float2(0.f, 0.f);
            if (gm < N_NODES) v = *(const float2*)&x[gm * D_FEAT + k];
            *(__half2*)&sX[m * KPAD + k] = __floats2half2_rn(v.x, v.y);
        }
        __syncthreads();

        float acc[2][8][4];
        #pragma unroll
        for (int mt = 0; mt < 2; mt++)
            #pragma unroll
            for (int nt = 0; nt < 8; nt++)
                #pragma unroll
                for (int r = 0; r < 4; r++) acc[mt][nt][r] = 0.f;

        #pragma unroll
        for (int ks = 0; ks < 8; ks++) {
            uint32_t a[2][4];
            ldsm_x4(a[0], aoff[0] + ks * 32);          // +16 halves per ks
            ldsm_x4(a[1], aoff[1] + ks * 32);
            #pragma unroll
            for (int p = 0; p < 4; p++) {
                uint32_t br[4];
                ldsm_x4_t(br, boff[p] + ks * 16 * KPADB);  // +16 k-rows per ks
                mma_fp16(acc[0][p * 2],     a[0], br[0], br[1]);
                mma_fp16(acc[1][p * 2],     a[1], br[0], br[1]);
                mma_fp16(acc[0][p * 2 + 1], a[0], br[2], br[3]);
                mma_fp16(acc[1][p * 2 + 1], a[1], br[2], br[3]);
            }
        }

        // epilogue: +b1 (A-half), fp16 store
        #pragma unroll
        for (int mt = 0; mt < 2; mt++) {
            const int node0 = m_block + mrow0 + mt * 16 + g;
            const int node1 = node0 + 8;
            #pragma unroll
            for (int nt = 0; nt < 8; nt++) {
                const int c = nloc0 + nt * 8 + t * 2;
                if (node0 < N_NODES)
                    *(__half2*)&halfp[(size_t)node0 * HIDDEN + c] =
                        __floats2half2_rn(acc[mt][nt][0] + bb[nt].x, acc[mt][nt][1] + bb[nt].y);
                if (node1 < N_NODES)
                    *(__half2*)&halfp[(size_t)node1 * HIDDEN + c] =
                        __floats2half2_rn(acc[mt][nt][2] + bb[nt].x, acc[mt][nt][3] + bb[nt].y);
            }
        }
        __syncthreads();   // protect sX before next tile's load
    }
}

// ---------------------------------------------------------------------------
// Stage 2 (R5 form, measured 37 us): half-warp per edge, 2 edges per
// half-warp per iteration (4 row-gathers in flight per half-warp).
// ---------------------------------------------------------------------------
static __device__ __forceinline__ float tanh_fast(float x) {
    float y;
    asm("tanh.approx.f32 %0, %1;" : "=f"(y) : "f"(x));
    return y;
}

__global__ __launch_bounds__(256) void edge_kernel(
    const void*  __restrict__ idx,
    const float* __restrict__ W2,
    const float* __restrict__ b2,
    float*       __restrict__ out,
    int E)
{
    const int lane = threadIdx.x & 31;
    const int hw   = lane >> 4;
    const int hl   = lane & 15;
    const int gwarp = (blockIdx.x * blockDim.x + threadIdx.x) >> 5;
    const int nwarps = (gridDim.x * blockDim.x) >> 5;

    const int* w32 = (const int*)idx;
    const bool is64 = ((w32[1] | w32[3] | w32[5] | w32[7]) == 0);
    const long long* p64 = (const long long*)idx;

    float wv[8];
    {
        float4 w0 = *(const float4*)&W2[hl * 8];
        float4 w1 = *(const float4*)&W2[hl * 8 + 4];
        wv[0] = w0.x; wv[1] = w0.y; wv[2] = w0.z; wv[3] = w0.w;
        wv[4] = w1.x; wv[5] = w1.y; wv[6] = w1.z; wv[7] = w1.w;
    }
    const float bias2 = b2[0];

    const uint4* Au = (const uint4*)g_A;   // 16 uint4 per row
    const uint4* Bu = (const uint4*)g_B;

    const int Q = (E + 3) >> 2;            // quads of edges
    for (int p = gwarp; p < Q; p += nwarps) {
        const int e0 = p * 4 + hw * 2;
        const int e1 = e0 + 1;
        const bool v0 = (e0 < E), v1 = (e1 < E);
        const int c0 = v0 ? e0 : (E - 1);
        const int c1 = v1 ? e1 : (E - 1);

        int s0, d0, s1, d1;
        if (is64) {
            s0 = (int)p64[c0]; d0 = (int)p64[E + c0];
            s1 = (int)p64[c1]; d1 = (int)p64[E + c1];
        } else {
            s0 = w32[c0];      d0 = w32[E + c0];
            s1 = w32[c1];      d1 = w32[E + c1];
        }

        uint4 ua0 = Au[(size_t)s0 * 16 + hl];
        uint4 ub0 = Bu[(size_t)d0 * 16 + hl];
        uint4 ua1 = Au[(size_t)s1 * 16 + hl];
        uint4 ub1 = Bu[(size_t)d1 * 16 + hl];

        float acc0 = 0.f, acc1 = 0.f;
        {
            const uint32_t* pa0 = (const uint32_t*)&ua0;
            const uint32_t* pb0 = (const uint32_t*)&ub0;
            const uint32_t* pa1 = (const uint32_t*)&ua1;
            const uint32_t* pb1 = (const uint32_t*)&ub1;
            #pragma unroll
            for (int q = 0; q < 4; q++) {
                float2 af0 = __half22float2(*(const __half2*)&pa0[q]);
                float2 bf0 = __half22float2(*(const __half2*)&pb0[q]);
                float2 af1 = __half22float2(*(const __half2*)&pa1[q]);
                float2 bf1 = __half22float2(*(const __half2*)&pb1[q]);
                acc0 = fmaf(tanh_fast(af0.x + bf0.x), wv[q * 2],     acc0);
                acc0 = fmaf(tanh_fast(af0.y + bf0.y), wv[q * 2 + 1], acc0);
                acc1 = fmaf(tanh_fast(af1.x + bf1.x), wv[q * 2],     acc1);
                acc1 = fmaf(tanh_fast(af1.y + bf1.y), wv[q * 2 + 1], acc1);
            }
        }

        #pragma unroll
        for (int off = 8; off; off >>= 1) {
            acc0 += __shfl_xor_sync(0xffffffffu, acc0, off);
            acc1 += __shfl_xor_sync(0xffffffffu, acc1, off);
        }

        if (hl == 0) {
            if (v0) out[e0] = __fdividef(1.0f, 1.0f + __expf(-(acc0 + bias2)));
            if (v1) out[e1] = __fdividef(1.0f, 1.0f + __expf(-(acc1 + bias2)));
        }
    }
}

// ---------------------------------------------------------------------------
extern "C" void kernel_launch(void* const* d_in, const int* in_sizes, int n_in,
                              void* d_out, int out_size)
{
    const float* x   = (const float*)d_in[0];
    const void*  idx = d_in[1];
    const float* W1  = (const float*)d_in[2];
    const float* b1  = (const float*)d_in[3];
    const float* W2  = (const float*)d_in[4];
    const float* b2  = (const float*)d_in[5];
    float* out = (float*)d_out;

    const int E = in_sizes[1] / 2;

    cudaFuncSetAttribute(node_gemm_kernel,
                         cudaFuncAttributeMaxDynamicSharedMemorySize, SMEM_TOTAL);

    const int n_tiles = (N_NODES + M_TILE - 1) / M_TILE;   // 782
    node_gemm_kernel<<<296, 512, SMEM_TOTAL>>>(x, W1, b1, n_tiles);

    edge_kernel<<<1184, 256>>>(idx, W2, b2, out, E);
}

// round 9
// speedup vs baseline: 1.8246x; 1.2250x over previous
#include <cuda_runtime.h>
#include <cuda_fp16.h>
#include <cstdint>

#define N_NODES 100000
#define D_FEAT  128
#define HIDDEN  128
#define M_TILE  128
#define KPAD    136          // fp16 row stride (272 B): LDSM-conflict-free (17 mod 8 = 1)
#define KPADB   272          // bytes

// ---------------------------------------------------------------------------
// Global scratch.  A/B stored fp16 (51 MB working set -> L2-resident gathers).
// ---------------------------------------------------------------------------
__device__ __half g_A[N_NODES * HIDDEN];       // x @ W1[:128] + b1
__device__ __half g_B[N_NODES * HIDDEN];       // x @ W1[128:]

// ---------------------------------------------------------------------------
// Stage 1: persistent GEMM, register-pipelined X loads.
// grid = 148 (1 CTA/SM, reg-capped anyway); each CTA converts W1 once into
// k-major fp16 smem, then loops over M-tiles.  The NEXT tile's X block
// (32 fp32/thread as 8 float4) is LDG'd right after the current tile's smem
// store and consumed after the MMA phase -> load latency hidden.
// A frags via ldmatrix.x4, B frags via ldmatrix.x4.trans.
// SMEM: sW [256][KPAD] (69632 B) + sX [128][KPAD] (34816 B) = 104448 B.
// ---------------------------------------------------------------------------
#define SM_W 0
#define SM_X 69632
#define SMEM_TOTAL 104448

static __device__ __forceinline__ uint32_t smem_u32(const void* p) {
    uint32_t a;
    asm("{ .reg .u64 t; cvta.to.shared.u64 t, %1; cvt.u32.u64 %0, t; }" : "=r"(a) : "l"(p));
    return a;
}

static __device__ __forceinline__ void mma_fp16(
    float c[4], const uint32_t a[4], uint32_t b0, uint32_t b1)
{
    asm volatile(
        "mma.sync.aligned.m16n8k16.row.col.f32.f16.f16.f32 "
        "{%0,%1,%2,%3}, {%4,%5,%6,%7}, {%8,%9}, {%0,%1,%2,%3};"
        : "+f"(c[0]), "+f"(c[1]), "+f"(c[2]), "+f"(c[3])
        : "r"(a[0]), "r"(a[1]), "r"(a[2]), "r"(a[3]), "r"(b0), "r"(b1));
}

static __device__ __forceinline__ void ldsm_x4(uint32_t r[4], uint32_t addr)
{
    asm volatile("ldmatrix.sync.aligned.m8n8.x4.shared.b16 {%0,%1,%2,%3}, [%4];"
                 : "=r"(r[0]), "=r"(r[1]), "=r"(r[2]), "=r"(r[3]) : "r"(addr));
}
static __device__ __forceinline__ void ldsm_x4_t(uint32_t r[4], uint32_t addr)
{
    asm volatile("ldmatrix.sync.aligned.m8n8.x4.trans.shared.b16 {%0,%1,%2,%3}, [%4];"
                 : "=r"(r[0]), "=r"(r[1]), "=r"(r[2]), "=r"(r[3]) : "r"(addr));
}

__global__ __launch_bounds__(512) void node_gemm_kernel(
    const float* __restrict__ x,
    const float* __restrict__ W1,
    const float* __restrict__ b1,
    int n_tiles)
{
    extern __shared__ char smem[];
    __half* sW = (__half*)(smem + SM_W);
    __half* sX = (__half*)(smem + SM_X);
    const uint32_t wbase = smem_u32(sW);
    const uint32_t xbase = smem_u32(sX);

    const int tid = threadIdx.x;

    // ---- convert W1 once: sW[r][c] = fp16(W1[r][c]), contiguous both sides
    #pragma unroll 4
    for (int i = tid * 2; i < 256 * 128; i += 512 * 2) {
        int r = i >> 7, c = i & 127;
        float2 v = *(const float2*)&W1[i];
        *(__half2*)&sW[r * KPAD + c] = __floats2half2_rn(v.x, v.y);
    }

    // ---- warp geometry
    const int wid  = tid >> 5;
    const int lane = tid & 31;
    const int g    = lane >> 2;
    const int t    = lane & 3;
    const int mrow0 = (wid & 3) * 32;
    const int ncol0 = (wid >> 2) * 64;         // 0,64,128,192
    const bool isA  = (ncol0 < 128);
    const int nloc0 = isA ? ncol0 : (ncol0 - 128);
    const int krowb = isA ? 0 : 128;

    const int lrow = (lane & 7) + ((lane >> 3) & 1) * 8;
    const int lsel = lane >> 4;

    uint32_t aoff[2];
    #pragma unroll
    for (int mt = 0; mt < 2; mt++)
        aoff[mt] = xbase + (uint32_t)((mrow0 + mt * 16 + lrow) * KPADB + lsel * 16);
    uint32_t boff[4];
    #pragma unroll
    for (int p = 0; p < 4; p++)
        boff[p] = wbase + (uint32_t)((krowb + lrow) * KPADB + (nloc0 + p * 16 + lsel * 8) * 2);

    float2 bb[8];
    #pragma unroll
    for (int nt = 0; nt < 8; nt++) {
        if (isA) bb[nt] = *(const float2*)&b1[ncol0 + nt * 8 + t * 2];
        else     bb[nt] = make_float2(0.f, 0.f);
    }
    __half* halfp = isA ? g_A : g_B;

    // X prefetch mapping: per j, v = tid + j*512; m = v>>5, kq = v&31 (k = 4*kq)
    // ---- prologue: prefetch first tile
    float4 pf[8];
    int tile = blockIdx.x;
    if (tile < n_tiles) {
        const int m_block = tile * M_TILE;
        #pragma unroll
        for (int j = 0; j < 8; j++) {
            int v = tid + j * 512;
            int m = v >> 5, kq = v & 31;
            int gm = m_block + m;
            pf[j] = (gm < N_NODES) ? *(const float4*)&x[gm * D_FEAT + kq * 4]
                                   : make_float4(0.f, 0.f, 0.f, 0.f);
        }
    }

    for (; tile < n_tiles; tile += gridDim.x) {
        const int m_block = tile * M_TILE;

        // ---- commit prefetched X into smem (convert fp32 -> fp16)
        #pragma unroll
        for (int j = 0; j < 8; j++) {
            int v = tid + j * 512;
            int m = v >> 5, kq = v & 31;
            __half2* d = (__half2*)&sX[m * KPAD + kq * 4];
            d[0] = __floats2half2_rn(pf[j].x, pf[j].y);
            d[1] = __floats2half2_rn(pf[j].z, pf[j].w);
        }
        __syncthreads();

        // ---- issue next tile's prefetch (latency covered by MMA+epilogue)
        const int ntile = tile + gridDim.x;
        if (ntile < n_tiles) {
            const int nmb = ntile * M_TILE;
            #pragma unroll
            for (int j = 0; j < 8; j++) {
                int v = tid + j * 512;
                int m = v >> 5, kq = v & 31;
                int gm = nmb + m;
                pf[j] = (gm < N_NODES) ? *(const float4*)&x[gm * D_FEAT + kq * 4]
                                       : make_float4(0.f, 0.f, 0.f, 0.f);
            }
        }

        // ---- MMA
        float acc[2][8][4];
        #pragma unroll
        for (int mt = 0; mt < 2; mt++)
            #pragma unroll
            for (int nt = 0; nt < 8; nt++)
                #pragma unroll
                for (int r = 0; r < 4; r++) acc[mt][nt][r] = 0.f;

        #pragma unroll
        for (int ks = 0; ks < 8; ks++) {
            uint32_t a[2][4];
            ldsm_x4(a[0], aoff[0] + ks * 32);
            ldsm_x4(a[1], aoff[1] + ks * 32);
            #pragma unroll
            for (int p = 0; p < 4; p++) {
                uint32_t br[4];
                ldsm_x4_t(br, boff[p] + ks * 16 * KPADB);
                mma_fp16(acc[0][p * 2],     a[0], br[0], br[1]);
                mma_fp16(acc[1][p * 2],     a[1], br[0], br[1]);
                mma_fp16(acc[0][p * 2 + 1], a[0], br[2], br[3]);
                mma_fp16(acc[1][p * 2 + 1], a[1], br[2], br[3]);
            }
        }

        // ---- epilogue: +b1 (A-half), fp16 store
        #pragma unroll
        for (int mt = 0; mt < 2; mt++) {
            const int node0 = m_block + mrow0 + mt * 16 + g;
            const int node1 = node0 + 8;
            #pragma unroll
            for (int nt = 0; nt < 8; nt++) {
                const int c = nloc0 + nt * 8 + t * 2;
                if (node0 < N_NODES)
                    *(__half2*)&halfp[(size_t)node0 * HIDDEN + c] =
                        __floats2half2_rn(acc[mt][nt][0] + bb[nt].x, acc[mt][nt][1] + bb[nt].y);
                if (node1 < N_NODES)
                    *(__half2*)&halfp[(size_t)node1 * HIDDEN + c] =
                        __floats2half2_rn(acc[mt][nt][2] + bb[nt].x, acc[mt][nt][3] + bb[nt].y);
            }
        }
        __syncthreads();   // sX consumed; next iteration may overwrite
    }
}

// ---------------------------------------------------------------------------
// Stage 2 (R5 form): half-warp per edge, 2 edges per half-warp per iteration.
// 32-bit byte-offset addressing (row = 256 B) to avoid IMAD.WIDE chains.
// ---------------------------------------------------------------------------
static __device__ __forceinline__ float tanh_fast(float x) {
    float y;
    asm("tanh.approx.f32 %0, %1;" : "=f"(y) : "f"(x));
    return y;
}

__global__ __launch_bounds__(256) void edge_kernel(
    const void*  __restrict__ idx,
    const float* __restrict__ W2,
    const float* __restrict__ b2,
    float*       __restrict__ out,
    int E)
{
    const int lane = threadIdx.x & 31;
    const int hw   = lane >> 4;
    const int hl   = lane & 15;
    const int gwarp = (blockIdx.x * blockDim.x + threadIdx.x) >> 5;
    const int nwarps = (gridDim.x * blockDim.x) >> 5;

    const int* w32 = (const int*)idx;
    const bool is64 = ((w32[1] | w32[3] | w32[5] | w32[7]) == 0);
    const long long* p64 = (const long long*)idx;

    float wv[8];
    {
        float4 w0 = *(const float4*)&W2[hl * 8];
        float4 w1 = *(const float4*)&W2[hl * 8 + 4];
        wv[0] = w0.x; wv[1] = w0.y; wv[2] = w0.z; wv[3] = w0.w;
        wv[4] = w1.x; wv[5] = w1.y; wv[6] = w1.z; wv[7] = w1.w;
    }
    const float bias2 = b2[0];

    const char* Ab = (const char*)g_A;     // 256 B per row
    const char* Bb = (const char*)g_B;
    const uint32_t lo = (uint32_t)(hl * 16);

    const int Q = (E + 3) >> 2;            // quads of edges
    for (int p = gwarp; p < Q; p += nwarps) {
        const int e0 = p * 4 + hw * 2;
        const int e1 = e0 + 1;
        const bool v0 = (e0 < E), v1 = (e1 < E);
        const int c0 = v0 ? e0 : (E - 1);
        const int c1 = v1 ? e1 : (E - 1);

        int s0, d0, s1, d1;
        if (is64) {
            s0 = (int)p64[c0]; d0 = (int)p64[E + c0];
            s1 = (int)p64[c1]; d1 = (int)p64[E + c1];
        } else {
            s0 = w32[c0];      d0 = w32[E + c0];
            s1 = w32[c1];      d1 = w32[E + c1];
        }

        uint4 ua0 = *(const uint4*)(Ab + ((uint32_t)s0 << 8) + lo);
        uint4 ub0 = *(const uint4*)(Bb + ((uint32_t)d0 << 8) + lo);
        uint4 ua1 = *(const uint4*)(Ab + ((uint32_t)s1 << 8) + lo);
        uint4 ub1 = *(const uint4*)(Bb + ((uint32_t)d1 << 8) + lo);

        float acc0 = 0.f, acc1 = 0.f;
        {
            const uint32_t* pa0 = (const uint32_t*)&ua0;
            const uint32_t* pb0 = (const uint32_t*)&ub0;
            const uint32_t* pa1 = (const uint32_t*)&ua1;
            const uint32_t* pb1 = (const uint32_t*)&ub1;
            #pragma unroll
            for (int q = 0; q < 4; q++) {
                float2 af0 = __half22float2(*(const __half2*)&pa0[q]);
                float2 bf0 = __half22float2(*(const __half2*)&pb0[q]);
                float2 af1 = __half22float2(*(const __half2*)&pa1[q]);
                float2 bf1 = __half22float2(*(const __half2*)&pb1[q]);
                acc0 = fmaf(tanh_fast(af0.x + bf0.x), wv[q * 2],     acc0);
                acc0 = fmaf(tanh_fast(af0.y + bf0.y), wv[q * 2 + 1], acc0);
                acc1 = fmaf(tanh_fast(af1.x + bf1.x), wv[q * 2],     acc1);
                acc1 = fmaf(tanh_fast(af1.y + bf1.y), wv[q * 2 + 1], acc1);
            }
        }

        #pragma unroll
        for (int off = 8; off; off >>= 1) {
            acc0 += __shfl_xor_sync(0xffffffffu, acc0, off);
            acc1 += __shfl_xor_sync(0xffffffffu, acc1, off);
        }

        if (hl == 0) {
            if (v0) out[e0] = __fdividef(1.0f, 1.0f + __expf(-(acc0 + bias2)));
            if (v1) out[e1] = __fdividef(1.0f, 1.0f + __expf(-(acc1 + bias2)));
        }
    }
}

// ---------------------------------------------------------------------------
extern "C" void kernel_launch(void* const* d_in, const int* in_sizes, int n_in,
                              void* d_out, int out_size)
{
    const float* x   = (const float*)d_in[0];
    const void*  idx = d_in[1];
    const float* W1  = (const float*)d_in[2];
    const float* b1  = (const float*)d_in[3];
    const float* W2  = (const float*)d_in[4];
    const float* b2  = (const float*)d_in[5];
    float* out = (float*)d_out;

    const int E = in_sizes[1] / 2;

    cudaFuncSetAttribute(node_gemm_kernel,
                         cudaFuncAttributeMaxDynamicSharedMemorySize, SMEM_TOTAL);

    const int n_tiles = (N_NODES + M_TILE - 1) / M_TILE;   // 782
    node_gemm_kernel<<<148, 512, SMEM_TOTAL>>>(x, W1, b1, n_tiles);

    edge_kernel<<<1184, 256>>>(idx, W2, b2, out, E);
}